// round 4
// baseline (speedup 1.0000x reference)
#include <cuda_runtime.h>
#include <math.h>

// Problem constants
#define BATCH 64
#define SEQ   512
#define HID   1024
#define EMB   256
#define NCHAR 128

// Persistent-kernel geometry
#define GRID     128     // 4 batch-tiles x 32 j-tiles, 1 CTA/SM, < 148 SMs -> all resident wave 1
#define NTHREADS 128     // 4 warps = 1 per SMSP
#define BT       16      // batch rows per CTA
#define JT       32      // hidden rows per CTA

#define SH_STRIDE 20     // padded h-tile row stride (floats) -> conflict-free transpose staging
#define SMEM_FLOATS (HID*JT + HID*SH_STRIDE)
#define SMEM_BYTES  (SMEM_FLOATS * 4)

// Device-global scratch (no allocations allowed)
__device__ float g_U[NCHAR * HID];          // U = embeddings @ W_ih^T  (128 x 1024)
__device__ float g_h[2][BATCH * HID];       // ping-pong hidden state
__device__ unsigned g_count = 0;            // barrier arrival counter (self-resetting)
__device__ volatile unsigned g_sense = 0;   // barrier sense (even barrier count/launch -> returns to 0)

// ---------------------------------------------------------------------------
// Grid barrier: sense reversal. State (g_count=0, g_sense=0) is restored at
// kernel end provided the number of barriers per launch is EVEN (it is: 514).
// ---------------------------------------------------------------------------
__device__ __forceinline__ void grid_barrier(unsigned s) {
    __syncthreads();
    if (threadIdx.x == 0) {
        __threadfence();  // make this CTA's global writes visible before arrival
        if (atomicAdd(&g_count, 1u) == (unsigned)GRID - 1u) {
            g_count = 0;
            __threadfence();
            g_sense = s;
        } else {
            while (g_sense != s) { }
            __threadfence();
        }
    }
    __syncthreads();
}

// ---------------------------------------------------------------------------
// Kernel 0: U[c][j] = sum_e emb[c][e] * W_ih[j][e]
// One warp computes 32 outputs; lanes split the E=256 reduction (coalesced).
// ---------------------------------------------------------------------------
__global__ void u_kernel(const float* __restrict__ emb, const float* __restrict__ wih) {
    int gt   = blockIdx.x * blockDim.x + threadIdx.x;
    int warp = gt >> 5;
    int lane = gt & 31;
    int e0   = lane * 8;
    for (int i = 0; i < 32; i++) {
        int o = warp * 32 + i;          // 131072 outputs total
        int c = o >> 10;
        int j = o & 1023;
        const float4* ep = (const float4*)(emb + c * EMB + e0);
        const float4* wp = (const float4*)(wih + j * EMB + e0);
        float4 e1 = __ldg(ep),     e2 = __ldg(ep + 1);
        float4 w1 = __ldg(wp),     w2 = __ldg(wp + 1);
        float acc = e1.x*w1.x + e1.y*w1.y + e1.z*w1.z + e1.w*w1.w
                  + e2.x*w2.x + e2.y*w2.y + e2.z*w2.z + e2.w*w2.w;
        acc += __shfl_xor_sync(0xffffffffu, acc, 16);
        acc += __shfl_xor_sync(0xffffffffu, acc, 8);
        acc += __shfl_xor_sync(0xffffffffu, acc, 4);
        acc += __shfl_xor_sync(0xffffffffu, acc, 2);
        acc += __shfl_xor_sync(0xffffffffu, acc, 1);
        if (lane == 0) g_U[c * HID + j] = acc;
    }
}

// ---------------------------------------------------------------------------
// Persistent RNN scan kernel.
// CTA (tb, tj): batches [tb*16, tb*16+16), hidden rows [tj*32, tj*32+32).
// W_hh slice lives in SMEM transposed [k][jj] for the whole kernel.
// Per step: stage h tile to SMEM [k][bb] (stride 20 pad, conflict-free),
// compute 512 dot products with 4b x 4j register tiles and k-split 4,
// shuffle-reduce, add U[t[b,s]], tanh, write ping-pong global h, grid barrier.
// ---------------------------------------------------------------------------
__global__ void __launch_bounds__(NTHREADS, 1) rnn_kernel(
    const int*   __restrict__ tids,
    const float* __restrict__ whh,
    const float* __restrict__ h0,
    const float* __restrict__ wproj,
    const float* __restrict__ bproj,
    float*       __restrict__ out)
{
    extern __shared__ float smem[];
    float* sW = smem;              // [1024][32]  W_hh slice, transposed
    float* sH = smem + HID * JT;   // [1024][20]  h tile, transposed, padded

    const int tid = threadIdx.x;
    const int cta = blockIdx.x;
    const int tb  = cta >> 5;      // 0..3
    const int tj  = cta & 31;      // 0..31
    const int b0  = tb * BT;
    const int j0  = tj * JT;

    // --- one-time: load W_hh slice transposed into SMEM (coalesced LDG) ---
    for (int idx = tid; idx < JT * HID; idx += NTHREADS) {
        int jj = idx >> 10;
        int k  = idx & 1023;
        sW[k * JT + jj] = whh[(j0 + jj) * HID + k];
    }
    // --- one-time: init h ping buffer with broadcast h0 (this CTA's tile) ---
    for (int idx = tid; idx < BT * JT; idx += NTHREADS) {
        int bb = idx >> 5;
        int jj = idx & 31;
        g_h[0][(b0 + bb) * HID + (j0 + jj)] = h0[j0 + jj];
    }

    unsigned bsense = 0;
    bsense ^= 1; grid_barrier(bsense);              // barrier #1

    const int w  = tid >> 5;   // warp = batch group (4 batches each)
    const int l  = tid & 31;
    const int jg = l & 7;      // j group (4 j's each)
    const int ks = l >> 3;     // k slice (256 k's each)
    const int kbase = ks * 256;

    const float* pW = sW + jg * 4;
    const float* pH = sH + w * 4;

    for (int s = 0; s < SEQ; s++) {
        const int cur = s & 1;
        const int nxt = cur ^ 1;

        // ---- stage h tile: sH[k][bb] = h[b0+bb][k], bypassing L1 (.cg) ----
        {
            const float* hb = g_h[cur];
            const int bb  = tid & 15;
            const int kq0 = tid >> 4;    // 0..7
            const float* hrow = hb + (b0 + bb) * HID;
            float* shb = sH + bb;
            #pragma unroll 8
            for (int it = 0; it < 32; it++) {
                int k = (it * 8 + kq0) * 4;
                float4 v = __ldcg((const float4*)(hrow + k));
                shb[(k + 0) * SH_STRIDE] = v.x;
                shb[(k + 1) * SH_STRIDE] = v.y;
                shb[(k + 2) * SH_STRIDE] = v.z;
                shb[(k + 3) * SH_STRIDE] = v.w;
            }
        }
        __syncthreads();

        // ---- main 4x4 register-tiled partial GEMM over this lane's k slice ----
        float acc[4][4];
        #pragma unroll
        for (int i = 0; i < 4; i++)
            #pragma unroll
            for (int m = 0; m < 4; m++) acc[i][m] = 0.0f;

        #pragma unroll 4
        for (int kk = 0; kk < 256; kk++) {
            const int k = kbase + kk;
            float4 wv = *(const float4*)(pW + k * JT);         // 4 j's (conflict-free)
            float4 hv = *(const float4*)(pH + k * SH_STRIDE);  // 4 b's (warp broadcast)
            float ha[4] = {hv.x, hv.y, hv.z, hv.w};
            float wa[4] = {wv.x, wv.y, wv.z, wv.w};
            #pragma unroll
            for (int i = 0; i < 4; i++)
                #pragma unroll
                for (int m = 0; m < 4; m++)
                    acc[i][m] = fmaf(ha[i], wa[m], acc[i][m]);
        }

        // ---- reduce the 4 k-slices (lanes differ in bits 3,4) ----
        #pragma unroll
        for (int i = 0; i < 4; i++)
            #pragma unroll
            for (int m = 0; m < 4; m++) {
                acc[i][m] += __shfl_xor_sync(0xffffffffu, acc[i][m], 8);
                acc[i][m] += __shfl_xor_sync(0xffffffffu, acc[i][m], 16);
            }

        // ---- epilogue: lane handles batch row i == ks -> 4 outputs ----
        float r0 = 0.f, r1 = 0.f, r2 = 0.f, r3 = 0.f;
        #pragma unroll
        for (int i = 0; i < 4; i++)
            if (ks == i) { r0 = acc[i][0]; r1 = acc[i][1]; r2 = acc[i][2]; r3 = acc[i][3]; }

        const int b = b0 + w * 4 + ks;
        const int c = tids[b * SEQ + s];
        float4 uv = *(const float4*)(g_U + c * HID + j0 + jg * 4);
        float4 hn;
        hn.x = tanhf(r0 + uv.x);
        hn.y = tanhf(r1 + uv.y);
        hn.z = tanhf(r2 + uv.z);
        hn.w = tanhf(r3 + uv.w);
        *(float4*)(g_h[nxt] + b * HID + j0 + jg * 4) = hn;

        bsense ^= 1; grid_barrier(bsense);          // barriers #2..#513
    }

    // ---- final projection: out[b][c] = h_final[b] . W_proj[c] + b_proj[c] ----
    // After s = 511 the final h is in g_h[0]. CTA covers 16 b x 4 chars.
    if (tid < 64) {
        const int bb = tid >> 2;
        const int cc = tid & 3;
        const int b  = b0 + bb;
        const int c  = tj * 4 + cc;
        const float* hp = g_h[0] + b * HID;
        const float* wp = wproj + c * HID;
        float acc2 = 0.0f;
        #pragma unroll 4
        for (int k = 0; k < HID; k += 4) {
            float4 hv = __ldcg((const float4*)(hp + k));
            float4 wv = *(const float4*)(wp + k);
            acc2 += hv.x*wv.x + hv.y*wv.y + hv.z*wv.z + hv.w*wv.w;
        }
        out[b * NCHAR + c] = acc2 + bproj[c];
    }

    bsense ^= 1; grid_barrier(bsense);              // barrier #514 (even total -> g_sense back to 0)
}

// ---------------------------------------------------------------------------
// Launch: two kernels, graph-capturable, no allocations, no syncs.
// Inputs (metadata order): t, embeddings, W_ih, W_hh, h0, W_proj, b_proj.
// ---------------------------------------------------------------------------
extern "C" void kernel_launch(void* const* d_in, const int* in_sizes, int n_in,
                              void* d_out, int out_size)
{
    const int*   t     = (const int*)  d_in[0];
    const float* emb   = (const float*)d_in[1];
    const float* wih   = (const float*)d_in[2];
    const float* whh   = (const float*)d_in[3];
    const float* h0    = (const float*)d_in[4];
    const float* wproj = (const float*)d_in[5];
    const float* bproj = (const float*)d_in[6];
    float*       out   = (float*)d_out;

    cudaFuncSetAttribute(rnn_kernel, cudaFuncAttributeMaxDynamicSharedMemorySize, SMEM_BYTES);

    u_kernel<<<512, 256>>>(emb, wih);
    rnn_kernel<<<GRID, NTHREADS, SMEM_BYTES>>>(t, whh, h0, wproj, bproj, out);
}